// round 2
// baseline (speedup 1.0000x reference)
#include <cuda_runtime.h>
#include <cstdint>

#define CRF_B 256
#define CRF_T 512
#define CRF_L 64

typedef unsigned long long ull;

// ---- packed f32x2 helpers (Blackwell dual-FP32) ----
__device__ __forceinline__ ull pack2(float lo, float hi) {
    ull r; asm("mov.b64 %0, {%1, %2};" : "=l"(r) : "f"(lo), "f"(hi)); return r;
}
__device__ __forceinline__ void unpack2(ull v, float& lo, float& hi) {
    asm("mov.b64 {%0, %1}, %2;" : "=f"(lo), "=f"(hi) : "l"(v));
}
__device__ __forceinline__ ull fma2(ull a, ull b, ull c) {
    ull d; asm("fma.rn.f32x2 %0, %1, %2, %3;" : "=l"(d) : "l"(a), "l"(b), "l"(c)); return d;
}
__device__ __forceinline__ ull add2(ull a, ull b) {
    ull d; asm("add.rn.f32x2 %0, %1, %2;" : "=l"(d) : "l"(a), "l"(b)); return d;
}
__device__ __forceinline__ float rcp_fast(float x) {
    float r; asm("rcp.approx.f32 %0, %1;" : "=f"(r) : "f"(x)); return r;
}

// One CTA (2 warps, 64 threads) per batch row. Lane j = threadIdx.x owns
// output label j. State kept in prob domain; renormalized every 4 steps by
// the (stale) w[0] element — any positive scale is valid, and w[0] is free:
// it's the low half of the first LDS.128 of the matmul. Spread bound
// |alpha_j - alpha_0| <= 2*max|trans| + spread(emit) ~ 12 nats keeps
// everything inside fp32 range between renorms.
__global__ __launch_bounds__(64, 1)
void CRF_48266842472844_kernel(const float* __restrict__ y_true,
                               const float* __restrict__ y_pred,
                               const float* __restrict__ trans,
                               float* __restrict__ out) {
    const int tid  = threadIdx.x;
    const int lane = tid & 31;
    const int wid  = tid >> 5;
    const int j    = tid;           // label owned by this thread
    const int b    = blockIdx.x;

    __shared__ __align__(16) float qbuf[2][CRF_L];   // double-buffered state
    __shared__ unsigned smask[2][2];                 // one-hot ballot per warp, dbl-buf
    __shared__ float sred[2], pred_[2];              // epilogue partials

    // ---- E[:, j] = exp(trans[:, j]) packed over i in pairs: 32 f32x2 regs ----
    ull E[32];
#pragma unroll
    for (int k = 0; k < 32; k++) {
        float a = __expf(__ldg(&trans[(2 * k)     * CRF_L + j]));
        float c = __expf(__ldg(&trans[(2 * k + 1) * CRF_L + j]));
        E[k] = pack2(a, c);
    }

    const float* yp = y_pred + (size_t)b * CRF_T * CRF_L;
    const float* yt = y_true + (size_t)b * CRF_T * CRF_L;

    // ---- t = 0 init ----
    float e0 = yp[j], y0 = yt[j];
    float pacc = e0 * y0;                  // point-score partial (per lane)
    float v = __expf(e0);
    qbuf[0][j] = v;
    unsigned mk0 = __ballot_sync(0xffffffffu, y0 > 0.5f);
    if (lane == 0) smask[0][wid] = mk0;

    float pe[2], py[2];                    // 2-deep emission/one-hot prefetch
    pe[0] = yp[1 * CRF_L + j];  py[0] = yt[1 * CRF_L + j];
    pe[1] = yp[2 * CRF_L + j];  py[1] = yt[2 * CRF_L + j];

    float Macc = 0.0f;   // accumulated log normalization
    float ts   = 0.0f;   // transition score (computed redundantly on all lanes)
    int   prev = 0;
    __syncthreads();

#define STEP(t_, GATHER, CONSUME) do {                                        \
    const int _t  = (t_);                                                     \
    const int _pb = ((_t) & 1) ^ 1;      /* (t-1)&1 */                        \
    const int _rd = ((_t) + 1) & 1;                                           \
    const int _wr = (_t) & 1;                                                 \
    float e = pe[_pb], y = py[_pb];                                           \
    int tn = _t + 2; tn = (tn > CRF_T - 1) ? (CRF_T - 1) : tn;                \
    pe[_pb] = yp[tn * CRF_L + j];  py[_pb] = yt[tn * CRF_L + j];              \
    float g = __expf(e);                                                      \
    const ulonglong2* q2 = (const ulonglong2*)qbuf[_rd];                      \
    ulonglong2 qv0 = q2[0];                                                   \
    if (CONSUME) {                                                            \
        float mlo, mhi; unpack2(qv0.x, mlo, mhi); (void)mhi;                  \
        Macc += __logf(mlo);                                                  \
        g *= rcp_fast(mlo);                                                   \
    }                                                                         \
    ull a0 = 0ull, a1 = 0ull, a2 = 0ull, a3 = 0ull;                           \
    _Pragma("unroll")                                                         \
    for (int k = 0; k < 16; k++) {                                            \
        ulonglong2 qv = (k == 0) ? qv0 : q2[k];                               \
        if ((k & 1) == 0) { a0 = fma2(qv.x, E[2 * k],     a0);                \
                            a1 = fma2(qv.y, E[2 * k + 1], a1); }              \
        else              { a2 = fma2(qv.x, E[2 * k],     a2);                \
                            a3 = fma2(qv.y, E[2 * k + 1], a3); }              \
    }                                                                         \
    unsigned msk = __ballot_sync(0xffffffffu, y > 0.5f);                      \
    if (lane == 0) smask[_wr][wid] = msk;                                     \
    pacc = fmaf(e, y, pacc);                                                  \
    {   unsigned mA = smask[_rd][0], mB = smask[_rd][1];                      \
        int lab = mA ? (__ffs(mA) - 1) : (__ffs(mB) + 31);                    \
        if (GATHER) ts += __ldg(&trans[prev * CRF_L + lab]);                  \
        prev = lab; }                                                         \
    a0 = add2(a0, a1); a2 = add2(a2, a3); a0 = add2(a0, a2);                  \
    { float slo, shi; unpack2(a0, slo, shi); v = (slo + shi) * g; }           \
    qbuf[_wr][j] = v;                                                         \
    __syncthreads();                                                          \
} while (0)

    STEP(1, false, false);
    STEP(2, true,  false);
    STEP(3, true,  false);

#pragma unroll 1
    for (int gg = 0; gg < 127; gg++) {
        const int t4 = 4 * gg + 4;
        STEP(t4 + 0, true, true);    // renormalize by stale w[0]
        STEP(t4 + 1, true, false);
        STEP(t4 + 2, true, false);
        STEP(t4 + 3, true, false);
    }
#undef STEP

    // ---- epilogue: log_norm = Macc + log(sum_j v) ; combine scores ----
    float ssum = v, psum = pacc;
#pragma unroll
    for (int s = 16; s > 0; s >>= 1) {
        ssum += __shfl_xor_sync(0xffffffffu, ssum, s);
        psum += __shfl_xor_sync(0xffffffffu, psum, s);
    }
    if (lane == 0) { sred[wid] = ssum; pred_[wid] = psum; }
    __syncthreads();
    if (tid == 0) {
        float S = sred[0] + sred[1];
        float P = pred_[0] + pred_[1];
        out[b] = (Macc + logf(S)) - P - ts;   // -(point + trans - log_norm)
    }
}

extern "C" void kernel_launch(void* const* d_in, const int* in_sizes, int n_in,
                              void* d_out, int out_size) {
    const float* y_true = (const float*)d_in[0];
    const float* y_pred = (const float*)d_in[1];
    const float* trans  = (const float*)d_in[2];
    float* out = (float*)d_out;
    (void)in_sizes; (void)n_in; (void)out_size;
    CRF_48266842472844_kernel<<<CRF_B, 64>>>(y_true, y_pred, trans, out);
}

// round 3
// speedup vs baseline: 1.9935x; 1.9935x over previous
#include <cuda_runtime.h>
#include <cstdint>

#define CRF_B 256
#define CRF_T 512
#define CRF_L 64

typedef unsigned long long ull;

// ---- packed f32x2 helpers (Blackwell dual-FP32) ----
__device__ __forceinline__ ull pack2(float lo, float hi) {
    ull r; asm("mov.b64 %0, {%1, %2};" : "=l"(r) : "f"(lo), "f"(hi)); return r;
}
__device__ __forceinline__ void unpack2(ull v, float& lo, float& hi) {
    asm("mov.b64 {%0, %1}, %2;" : "=f"(lo), "=f"(hi) : "l"(v));
}
__device__ __forceinline__ ull fma2(ull a, ull b, ull c) {
    ull d; asm("fma.rn.f32x2 %0, %1, %2, %3;" : "=l"(d) : "l"(a), "l"(b), "l"(c)); return d;
}
__device__ __forceinline__ ull add2(ull a, ull b) {
    ull d; asm("add.rn.f32x2 %0, %1, %2;" : "=l"(d) : "l"(a), "l"(b)); return d;
}
__device__ __forceinline__ float rcp_fast(float x) {
    float r; asm("rcp.approx.f32 %0, %1;" : "=f"(r) : "f"(x)); return r;
}

// One CTA (3 warps) per batch row.
//   warp 0: forward recursion  alpha, t = 0..255   (255 matvec steps)
//   warp 1: backward recursion beta,  t = 511..255 (256 matvec steps)
//   warp 2: point score + transition score (fully parallel in t)
// No __syncthreads in any hot loop — single barrier at the end, then combine.
// State kept in prob domain; renormalized every 4 steps by the stale w[0]
// element (free: low half of the first LDS.128 of the matvec).
__global__ __launch_bounds__(96, 1)
void CRF_48266842472844_kernel(const float* __restrict__ y_true,
                               const float* __restrict__ y_pred,
                               const float* __restrict__ trans,
                               float* __restrict__ out) {
    const int tid  = threadIdx.x;
    const int lane = tid & 31;
    const int wid  = tid >> 5;
    const int b    = blockIdx.x;
    const int jA   = lane;
    const int jB   = lane + 32;

    __shared__ __align__(16) float qf[2][CRF_L];   // forward state (dbl buf)
    __shared__ __align__(16) float qb[2][CRF_L];   // backward state (dbl buf)
    __shared__ __align__(16) float bout[CRF_L];    // beta_255 (final backward)
    __shared__ int   labs[CRF_T];                  // per-t argmax labels
    __shared__ float sMb, sP, sTs;                 // backward M, point, trans

    const float* yp = y_pred + (size_t)b * CRF_T * CRF_L;
    const float* yt = y_true + (size_t)b * CRF_T * CRF_L;

    float vA = 0.0f, vB = 0.0f, M = 0.0f;   // live across the final barrier

// ---- shared matvec step core (64 fma2, 4 acc chains) ----
#define CORE(qread, qwrite, EA, EB, eA, eB, CONSUME) do {                     \
    float gA = __expf(eA), gB = __expf(eB);                                   \
    const ulonglong2* q2 = (const ulonglong2*)(qread);                        \
    ulonglong2 qv0 = q2[0];                                                   \
    if (CONSUME) {                                                            \
        float m0, mh; unpack2(qv0.x, m0, mh); (void)mh;                       \
        M += __logf(m0);                                                      \
        float r = rcp_fast(m0); gA *= r; gB *= r;                             \
    }                                                                         \
    ull a0 = 0ull, a1 = 0ull, b0 = 0ull, b1 = 0ull;                           \
    _Pragma("unroll")                                                         \
    for (int k = 0; k < 16; k++) {                                            \
        ulonglong2 qv = (k == 0) ? qv0 : q2[k];                               \
        a0 = fma2(qv.x, EA[2 * k],     a0);                                   \
        b0 = fma2(qv.x, EB[2 * k],     b0);                                   \
        a1 = fma2(qv.y, EA[2 * k + 1], a1);                                   \
        b1 = fma2(qv.y, EB[2 * k + 1], b1);                                   \
    }                                                                         \
    a0 = add2(a0, a1); b0 = add2(b0, b1);                                     \
    { float lo, hi; unpack2(a0, lo, hi); vA = (lo + hi) * gA;                 \
      unpack2(b0, lo, hi); vB = (lo + hi) * gB; }                             \
    (qwrite)[jA] = vA; (qwrite)[jB] = vB;                                     \
    __syncwarp();                                                             \
} while (0)

    if (wid == 0) {
        // ================= FORWARD: alpha_t, t = 0 .. 255 =================
        ull Ea[32], Eb[32];   // E[:, jA], E[:, jB] packed over i-pairs
#pragma unroll
        for (int k = 0; k < 32; k++) {
            Ea[k] = pack2(__expf(__ldg(&trans[(2 * k)     * CRF_L + jA])),
                          __expf(__ldg(&trans[(2 * k + 1) * CRF_L + jA])));
            Eb[k] = pack2(__expf(__ldg(&trans[(2 * k)     * CRF_L + jB])),
                          __expf(__ldg(&trans[(2 * k + 1) * CRF_L + jB])));
        }
        vA = __expf(yp[jA]);
        vB = __expf(yp[jB]);
        qf[0][jA] = vA; qf[0][jB] = vB;

        float peA[2], peB[2];
        peA[0] = yp[1 * CRF_L + jA]; peB[0] = yp[1 * CRF_L + jB];
        peA[1] = yp[2 * CRF_L + jA]; peB[1] = yp[2 * CRF_L + jB];
        int cur = 0;
        __syncwarp();

#define FSTEP(t_, CONSUME) do {                                               \
    const int _pb = ((t_) - 1) & 1;                                           \
    float eA = peA[_pb], eB = peB[_pb];                                       \
    int tn = (t_) + 2; tn = (tn > 255) ? 255 : tn;                            \
    peA[_pb] = yp[tn * CRF_L + jA]; peB[_pb] = yp[tn * CRF_L + jB];           \
    const float* qr = qf[cur]; float* qw = qf[cur ^ 1]; cur ^= 1;             \
    CORE(qr, qw, Ea, Eb, eA, eB, CONSUME);                                    \
} while (0)

        FSTEP(1, false); FSTEP(2, false); FSTEP(3, false);
#pragma unroll 1
        for (int g4 = 0; g4 < 63; g4++) {
            const int t4 = 4 * g4 + 4;
            FSTEP(t4 + 0, true);
            FSTEP(t4 + 1, false);
            FSTEP(t4 + 2, false);
            FSTEP(t4 + 3, false);
        }
#undef FSTEP
        // vA, vB now hold alpha~_255 ; M holds Macc_f

    } else if (wid == 1) {
        // ================= BACKWARD: beta_t, t = 511 .. 255 ===============
        ull Ea[32], Eb[32];   // E[jA, :], E[jB, :] packed over j-pairs (rows)
#pragma unroll
        for (int m = 0; m < 16; m++) {
            float4 ra = __ldg((const float4*)&trans[jA * CRF_L + 4 * m]);
            Ea[2 * m]     = pack2(__expf(ra.x), __expf(ra.y));
            Ea[2 * m + 1] = pack2(__expf(ra.z), __expf(ra.w));
            float4 rb = __ldg((const float4*)&trans[jB * CRF_L + 4 * m]);
            Eb[2 * m]     = pack2(__expf(rb.x), __expf(rb.y));
            Eb[2 * m + 1] = pack2(__expf(rb.z), __expf(rb.w));
        }
        // u_511 = g_511 (beta_511 = 1)
        vA = __expf(yp[511 * CRF_L + jA]);
        vB = __expf(yp[511 * CRF_L + jB]);
        qb[0][jA] = vA; qb[0][jB] = vB;

        float peA[2], peB[2];   // slot = t & 1 (510 even -> slot 0)
        peA[0] = yp[510 * CRF_L + jA]; peB[0] = yp[510 * CRF_L + jB];
        peA[1] = yp[509 * CRF_L + jA]; peB[1] = yp[509 * CRF_L + jB];
        int cur = 0;
        __syncwarp();

#define BSTEP(t_, CONSUME) do {                                               \
    const int _pb = (t_) & 1;                                                 \
    float eA = peA[_pb], eB = peB[_pb];                                       \
    int tn = (t_) - 2; tn = (tn < 255) ? 255 : tn;                            \
    peA[_pb] = yp[tn * CRF_L + jA]; peB[_pb] = yp[tn * CRF_L + jB];           \
    const float* qr = qb[cur]; float* qw = qb[cur ^ 1]; cur ^= 1;             \
    CORE(qr, qw, Ea, Eb, eA, eB, CONSUME);                                    \
} while (0)

        BSTEP(510, false); BSTEP(509, false); BSTEP(508, false);
#pragma unroll 1
        for (int g4 = 0; g4 < 63; g4++) {
            const int tg = 507 - 4 * g4;
            BSTEP(tg - 0, true);
            BSTEP(tg - 1, false);
            BSTEP(tg - 2, false);
            BSTEP(tg - 3, false);
        }
#undef BSTEP
        // final step: beta_255 = E u_256, with renorm, NO g multiply
        {
            const ulonglong2* q2 = (const ulonglong2*)qb[cur];
            ulonglong2 qv0 = q2[0];
            float m0, mh; unpack2(qv0.x, m0, mh); (void)mh;
            M += __logf(m0);
            float r = rcp_fast(m0);
            ull a0 = 0ull, a1 = 0ull, b0 = 0ull, b1 = 0ull;
#pragma unroll
            for (int k = 0; k < 16; k++) {
                ulonglong2 qv = (k == 0) ? qv0 : q2[k];
                a0 = fma2(qv.x, Ea[2 * k],     a0);
                b0 = fma2(qv.x, Eb[2 * k],     b0);
                a1 = fma2(qv.y, Ea[2 * k + 1], a1);
                b1 = fma2(qv.y, Eb[2 * k + 1], b1);
            }
            a0 = add2(a0, a1); b0 = add2(b0, b1);
            float lo, hi;
            unpack2(a0, lo, hi); bout[jA] = (lo + hi) * r;
            unpack2(b0, lo, hi); bout[jB] = (lo + hi) * r;
        }
        if (lane == 0) sMb = M;

    } else {
        // ================= SCORES: point + transition =====================
        const float4* yp4 = (const float4*)yp;
        const float4* yt4 = (const float4*)yt;
        const int half = lane >> 4, l4 = lane & 15;
        float pacc = 0.0f;
#pragma unroll 4
        for (int t = 0; t < CRF_T; t += 2) {
            const int tt = t + half;
            float4 p = yp4[tt * 16 + l4];
            float4 q = yt4[tt * 16 + l4];
            pacc += p.x * q.x + p.y * q.y + p.z * q.z + p.w * q.w;
            int c = -1;
            if      (q.x > 0.5f) c = 0;
            else if (q.y > 0.5f) c = 1;
            else if (q.z > 0.5f) c = 2;
            else if (q.w > 0.5f) c = 3;
            unsigned m  = __ballot_sync(0xffffffffu, c >= 0);
            unsigned mh = (m >> (half * 16)) & 0xffffu;
            int src = half * 16 + (__ffs(mh) - 1);
            int lab = __shfl_sync(0xffffffffu, 4 * l4 + c, src);
            if (l4 == 0) labs[tt] = lab;
        }
        __syncwarp();
        float ts = 0.0f;
#pragma unroll 4
        for (int t0 = lane; t0 < CRF_T - 1; t0 += 32)
            ts += __ldg(&trans[labs[t0] * CRF_L + labs[t0 + 1]]);
#pragma unroll
        for (int s = 16; s > 0; s >>= 1) {
            pacc += __shfl_xor_sync(0xffffffffu, pacc, s);
            ts   += __shfl_xor_sync(0xffffffffu, ts, s);
        }
        if (lane == 0) { sP = pacc; sTs = ts; }
    }

    __syncthreads();

    // ================= COMBINE (warp 0) ==================================
    if (wid == 0) {
        float dot = vA * bout[jA] + vB * bout[jB];
#pragma unroll
        for (int s = 16; s > 0; s >>= 1)
            dot += __shfl_xor_sync(0xffffffffu, dot, s);
        if (lane == 0)
            out[b] = (M + sMb + logf(dot)) - sP - sTs;  // -(P + TS - logZ)
    }
#undef CORE
}

extern "C" void kernel_launch(void* const* d_in, const int* in_sizes, int n_in,
                              void* d_out, int out_size) {
    const float* y_true = (const float*)d_in[0];
    const float* y_pred = (const float*)d_in[1];
    const float* trans  = (const float*)d_in[2];
    float* out = (float*)d_out;
    (void)in_sizes; (void)n_in; (void)out_size;
    CRF_48266842472844_kernel<<<CRF_B, 96>>>(y_true, y_pred, trans, out);
}

// round 4
// speedup vs baseline: 3.1282x; 1.5692x over previous
#include <cuda_runtime.h>
#include <cstdint>

#define CRF_B 256
#define CRF_T 512
#define CRF_L 64

typedef unsigned long long ull;

// ---- packed f32x2 helpers (Blackwell dual-FP32) ----
__device__ __forceinline__ ull pack2(float lo, float hi) {
    ull r; asm("mov.b64 %0, {%1, %2};" : "=l"(r) : "f"(lo), "f"(hi)); return r;
}
__device__ __forceinline__ void unpack2(ull v, float& lo, float& hi) {
    asm("mov.b64 {%0, %1}, %2;" : "=f"(lo), "=f"(hi) : "l"(v));
}
__device__ __forceinline__ ull fma2(ull a, ull b, ull c) {
    ull d; asm("fma.rn.f32x2 %0, %1, %2, %3;" : "=l"(d) : "l"(a), "l"(b), "l"(c)); return d;
}
__device__ __forceinline__ ull add2(ull a, ull b) {
    ull d; asm("add.rn.f32x2 %0, %1, %2;" : "=l"(d) : "l"(a), "l"(b)); return d;
}
__device__ __forceinline__ float rcp_fast(float x) {
    float r; asm("rcp.approx.f32 %0, %1;" : "=f"(r) : "f"(x)); return r;
}

// 128 CTAs (1 per SM), 2 batch rows per CTA, 8 warps:
//   wid 0: fwd row0 (SMSP0)   wid 1: bwd row0 (SMSP1)
//   wid 2: fwd row1 (SMSP2)   wid 3: bwd row1 (SMSP3)
//   wid 4-7: scores (one per SMSP; row = (wid-4)>>1, t-half = (wid-4)&1)
// Heavy warps are barrier-free (syncwarp only). Score warps use a named
// barrier (id 1) among themselves. One __syncthreads at the end.
__global__ __launch_bounds__(256, 1)
void CRF_48266842472844_kernel(const float* __restrict__ y_true,
                               const float* __restrict__ y_pred,
                               const float* __restrict__ trans,
                               float* __restrict__ out) {
    const int tid  = threadIdx.x;
    const int lane = tid & 31;
    const int wid  = tid >> 5;
    const int jA   = lane;
    const int jB   = lane + 32;

    __shared__ __align__(16) float qf[2][2][CRF_L];   // [row][buf][label]
    __shared__ __align__(16) float qb[2][2][CRF_L];
    __shared__ __align__(16) float bout[2][CRF_L];    // beta_255 per row
    __shared__ int   labs[2][CRF_T];
    __shared__ float sMb[2], sP[2][2], sTs[2][2];

    float vA = 0.0f, vB = 0.0f, M = 0.0f;   // live across final barrier

#define CORE(qread, qwrite, EA, EB, eA, eB, CONSUME) do {                     \
    float gA = __expf(eA), gB = __expf(eB);                                   \
    const ulonglong2* q2 = (const ulonglong2*)(qread);                        \
    ulonglong2 qv0 = q2[0];                                                   \
    if (CONSUME) {                                                            \
        float m0, mh; unpack2(qv0.x, m0, mh); (void)mh;                       \
        M += __logf(m0);                                                      \
        float r = rcp_fast(m0); gA *= r; gB *= r;                             \
    }                                                                         \
    ull a0 = 0ull, a1 = 0ull, b0 = 0ull, b1 = 0ull;                           \
    _Pragma("unroll")                                                         \
    for (int k = 0; k < 16; k++) {                                            \
        ulonglong2 qv = (k == 0) ? qv0 : q2[k];                               \
        a0 = fma2(qv.x, EA[2 * k],     a0);                                   \
        b0 = fma2(qv.x, EB[2 * k],     b0);                                   \
        a1 = fma2(qv.y, EA[2 * k + 1], a1);                                   \
        b1 = fma2(qv.y, EB[2 * k + 1], b1);                                   \
    }                                                                         \
    a0 = add2(a0, a1); b0 = add2(b0, b1);                                     \
    { float lo, hi; unpack2(a0, lo, hi); vA = (lo + hi) * gA;                 \
      unpack2(b0, lo, hi); vB = (lo + hi) * gB; }                             \
    (qwrite)[jA] = vA; (qwrite)[jB] = vB;                                     \
    __syncwarp();                                                             \
} while (0)

    if (wid < 4) {
        const int row  = wid >> 1;          // 0 or 1
        const int kind = wid & 1;           // 0 = fwd, 1 = bwd
        const int b    = 2 * blockIdx.x + row;
        const float* yp = y_pred + (size_t)b * CRF_T * CRF_L;

        if (kind == 0) {
            // ============== FORWARD: alpha_t, t = 0 .. 255 ==============
            ull Ea[32], Eb[32];   // E[:, jA], E[:, jB] packed over i-pairs
#pragma unroll
            for (int k = 0; k < 32; k++) {
                Ea[k] = pack2(__expf(__ldg(&trans[(2 * k)     * CRF_L + jA])),
                              __expf(__ldg(&trans[(2 * k + 1) * CRF_L + jA])));
                Eb[k] = pack2(__expf(__ldg(&trans[(2 * k)     * CRF_L + jB])),
                              __expf(__ldg(&trans[(2 * k + 1) * CRF_L + jB])));
            }
            vA = __expf(yp[jA]);
            vB = __expf(yp[jB]);
            qf[row][0][jA] = vA; qf[row][0][jB] = vB;

            float peA[2], peB[2];
            peA[0] = yp[1 * CRF_L + jA]; peB[0] = yp[1 * CRF_L + jB];
            peA[1] = yp[2 * CRF_L + jA]; peB[1] = yp[2 * CRF_L + jB];
            int cur = 0;
            __syncwarp();

#define FSTEP(t_, CONSUME) do {                                               \
    const int _pb = ((t_) - 1) & 1;                                           \
    float eA = peA[_pb], eB = peB[_pb];                                       \
    int tn = (t_) + 2; tn = (tn > 255) ? 255 : tn;                            \
    peA[_pb] = yp[tn * CRF_L + jA]; peB[_pb] = yp[tn * CRF_L + jB];           \
    const float* qr = qf[row][cur]; float* qw = qf[row][cur ^ 1]; cur ^= 1;   \
    CORE(qr, qw, Ea, Eb, eA, eB, CONSUME);                                    \
} while (0)

            FSTEP(1, false); FSTEP(2, false); FSTEP(3, false);
#pragma unroll 1
            for (int g4 = 0; g4 < 63; g4++) {
                const int t4 = 4 * g4 + 4;
                FSTEP(t4 + 0, true);
                FSTEP(t4 + 1, false);
                FSTEP(t4 + 2, false);
                FSTEP(t4 + 3, false);
            }
#undef FSTEP
            // vA, vB = alpha~_255 ; M = Macc_f
        } else {
            // ============== BACKWARD: beta_t, t = 511 .. 255 ============
            ull Ea[32], Eb[32];   // E[jA, :], E[jB, :] packed over j-pairs
#pragma unroll
            for (int m = 0; m < 16; m++) {
                float4 ra = __ldg((const float4*)&trans[jA * CRF_L + 4 * m]);
                Ea[2 * m]     = pack2(__expf(ra.x), __expf(ra.y));
                Ea[2 * m + 1] = pack2(__expf(ra.z), __expf(ra.w));
                float4 rb = __ldg((const float4*)&trans[jB * CRF_L + 4 * m]);
                Eb[2 * m]     = pack2(__expf(rb.x), __expf(rb.y));
                Eb[2 * m + 1] = pack2(__expf(rb.z), __expf(rb.w));
            }
            vA = __expf(yp[511 * CRF_L + jA]);
            vB = __expf(yp[511 * CRF_L + jB]);
            qb[row][0][jA] = vA; qb[row][0][jB] = vB;

            float peA[2], peB[2];   // slot = t & 1
            peA[0] = yp[510 * CRF_L + jA]; peB[0] = yp[510 * CRF_L + jB];
            peA[1] = yp[509 * CRF_L + jA]; peB[1] = yp[509 * CRF_L + jB];
            int cur = 0;
            __syncwarp();

#define BSTEP(t_, CONSUME) do {                                               \
    const int _pb = (t_) & 1;                                                 \
    float eA = peA[_pb], eB = peB[_pb];                                       \
    int tn = (t_) - 2; tn = (tn < 255) ? 255 : tn;                            \
    peA[_pb] = yp[tn * CRF_L + jA]; peB[_pb] = yp[tn * CRF_L + jB];           \
    const float* qr = qb[row][cur]; float* qw = qb[row][cur ^ 1]; cur ^= 1;   \
    CORE(qr, qw, Ea, Eb, eA, eB, CONSUME);                                    \
} while (0)

            BSTEP(510, false); BSTEP(509, false); BSTEP(508, false);
#pragma unroll 1
            for (int g4 = 0; g4 < 63; g4++) {
                const int tg = 507 - 4 * g4;
                BSTEP(tg - 0, true);
                BSTEP(tg - 1, false);
                BSTEP(tg - 2, false);
                BSTEP(tg - 3, false);
            }
#undef BSTEP
            // final: beta_255 = E u_256 (renorm, no g multiply)
            {
                const ulonglong2* q2 = (const ulonglong2*)qb[row][cur];
                ulonglong2 qv0 = q2[0];
                float m0, mh; unpack2(qv0.x, m0, mh); (void)mh;
                M += __logf(m0);
                float r = rcp_fast(m0);
                ull a0 = 0ull, a1 = 0ull, b0 = 0ull, b1 = 0ull;
#pragma unroll
                for (int k = 0; k < 16; k++) {
                    ulonglong2 qv = (k == 0) ? qv0 : q2[k];
                    a0 = fma2(qv.x, Ea[2 * k],     a0);
                    b0 = fma2(qv.x, Eb[2 * k],     b0);
                    a1 = fma2(qv.y, Ea[2 * k + 1], a1);
                    b1 = fma2(qv.y, Eb[2 * k + 1], b1);
                }
                a0 = add2(a0, a1); b0 = add2(b0, b1);
                float lo, hi;
                unpack2(a0, lo, hi); bout[row][jA] = (lo + hi) * r;
                unpack2(b0, lo, hi); bout[row][jB] = (lo + hi) * r;
            }
            if (lane == 0) sMb[row] = M;
        }
    } else {
        // ================= SCORES (wid 4-7) ==============================
        const int sw   = wid - 4;
        const int row  = sw >> 1;          // row 0: wid 4,5 ; row 1: wid 6,7
        const int half_t = sw & 1;         // t-half: [0,256) or [256,512)
        const int b    = 2 * blockIdx.x + row;
        const float* yp = y_pred + (size_t)b * CRF_T * CRF_L;
        const float* yt = y_true + (size_t)b * CRF_T * CRF_L;
        const float4* yp4 = (const float4*)yp;
        const float4* yt4 = (const float4*)yt;
        const int base = half_t * 256;
        const int hh = lane >> 4, l4 = lane & 15;

        float pacc = 0.0f;
#pragma unroll 4
        for (int t = base; t < base + 256; t += 2) {
            const int tt = t + hh;
            float4 p = yp4[tt * 16 + l4];
            float4 q = yt4[tt * 16 + l4];
            pacc += p.x * q.x + p.y * q.y + p.z * q.z + p.w * q.w;
            int c = -1;
            if      (q.x > 0.5f) c = 0;
            else if (q.y > 0.5f) c = 1;
            else if (q.z > 0.5f) c = 2;
            else if (q.w > 0.5f) c = 3;
            unsigned m  = __ballot_sync(0xffffffffu, c >= 0);
            unsigned mh = (m >> (hh * 16)) & 0xffffu;
            int src = hh * 16 + (__ffs(mh) - 1);
            int lab = __shfl_sync(0xffffffffu, 4 * l4 + c, src);
            if (l4 == 0) labs[row][tt] = lab;
        }
        // stitch label array across the 4 score warps
        asm volatile("bar.sync 1, 128;" ::: "memory");

        float ts = 0.0f;
        const int tmax = half_t ? (CRF_T - 1) : 256;
#pragma unroll 4
        for (int t0 = base + lane; t0 < tmax; t0 += 32)
            ts += __ldg(&trans[labs[row][t0] * CRF_L + labs[row][t0 + 1]]);
#pragma unroll
        for (int s = 16; s > 0; s >>= 1) {
            pacc += __shfl_xor_sync(0xffffffffu, pacc, s);
            ts   += __shfl_xor_sync(0xffffffffu, ts, s);
        }
        if (lane == 0) { sP[row][half_t] = pacc; sTs[row][half_t] = ts; }
    }

    __syncthreads();

    // ================= COMBINE: fwd warps (wid 0, 2) =====================
    if (wid < 4 && (wid & 1) == 0) {
        const int row = wid >> 1;
        float dot = vA * bout[row][jA] + vB * bout[row][jB];
#pragma unroll
        for (int s = 16; s > 0; s >>= 1)
            dot += __shfl_xor_sync(0xffffffffu, dot, s);
        if (lane == 0) {
            float P  = sP[row][0] + sP[row][1];
            float TS = sTs[row][0] + sTs[row][1];
            out[2 * blockIdx.x + row] = (M + sMb[row] + logf(dot)) - P - TS;
        }
    }
#undef CORE
}

extern "C" void kernel_launch(void* const* d_in, const int* in_sizes, int n_in,
                              void* d_out, int out_size) {
    const float* y_true = (const float*)d_in[0];
    const float* y_pred = (const float*)d_in[1];
    const float* trans  = (const float*)d_in[2];
    float* out = (float*)d_out;
    (void)in_sizes; (void)n_in; (void)out_size;
    CRF_48266842472844_kernel<<<CRF_B / 2, 256>>>(y_true, y_pred, trans, out);
}